// round 11
// baseline (speedup 1.0000x reference)
#include <cuda_runtime.h>
#include <cuda_bf16.h>

// 4096 possible 12-bit rows -> 32 floats each = 512 KB LUT in device global.
__device__ float g_lut[4096 * 32];

#define ROWS_PER_BLOCK 128
#define THREADS 256

// ---- LUT build kernel: 128 blocks x 128 threads = 16384 (b, s) items ----
// Trigger for dependent launch fires AFTER the LUT stores (+fence), so the
// gather's griddepcontrol.wait guarantees LUT visibility.
__global__ __launch_bounds__(128)
void build_lut_kernel(const float* __restrict__ pat,
                      const float* __restrict__ pos,
                      const int*   __restrict__ conn)
{
    __shared__ int s_conn[240];
    // FIX (R9/R10 bug): block has 128 threads; loop to cover all 240 entries.
    for (int i = threadIdx.x; i < 240; i += 128)
        s_conn[i] = __ldg(&conn[i]);
    __syncthreads();

    const int idx = blockIdx.x * 128 + threadIdx.x;
    const int b = idx >> 2;
    const int s = idx & 3;

    const int bits3n = 3 * (s + 1);
    const int paddr  = b & ((1 << bits3n) - 1);   // last 3n columns, MSB-first

    float out[8];
    int pb = 0;
#pragma unroll
    for (int j = 0; j < 3; j++) {
        float v = __ldg(&pat[(s * 3 + j) * 4096 + paddr]);
        int bit = (v > 0.5f) ? 1 : 0;
        out[j]  = (float)bit;
        pb |= bit << j;
    }

    const int in_bits = bits3n + 3;
    const int nb      = (in_bits < 12) ? in_bits : 12;
#pragma unroll
    for (int k = 0; k < 5; k++) {
        int addr = 0;
        for (int j = 0; j < nb; j++) {
            int c   = s_conn[(s * 5 + k) * 12 + j] % in_bits;
            int bit = (c < bits3n) ? ((paddr >> (bits3n - 1 - c)) & 1)
                                   : ((pb >> (c - bits3n)) & 1);
            addr |= bit << j;
        }
        out[3 + k] = __ldg(&pos[(s * 5 + k) * 4096 + addr]);
    }

    float4* dst = (float4*)&g_lut[b * 32 + s * 8];
    dst[0] = ((const float4*)out)[0];
    dst[1] = ((const float4*)out)[1];

    // Publish, THEN trigger dependent launch (only pre-trigger writes are
    // guaranteed visible to the dependent grid after its wait).
    __threadfence();
    asm volatile("griddepcontrol.launch_dependents;" ::: "memory");
}

// ---- Gather kernel (R3 hot path, unchanged) + griddepcontrol.wait ----
// Block of 256 handles 128 rows:
//   stage1: coalesced int4 input staging to smem   (no LUT dependence)
//   stage2: 12-bit MSB-first pack per row          (no LUT dependence)
//   [PDL wait: LUT guaranteed visible]
//   stage3: MLP=4 LUT gather + fully coalesced streaming stores
__global__ __launch_bounds__(THREADS)
void gather_kernel(const int* __restrict__ tb,
                   float* __restrict__ out,
                   int nrows)
{
    __shared__ int s_bits[ROWS_PER_BLOCK * 12];   // 6144 B
    __shared__ int s_idx[ROWS_PER_BLOCK];

    const int tid      = threadIdx.x;
    const int row_base = blockIdx.x * ROWS_PER_BLOCK;
    const int rows     = min(ROWS_PER_BLOCK, nrows - row_base);
    if (rows <= 0) {
        asm volatile("griddepcontrol.wait;" ::: "memory");
        return;
    }

    // Stage 1: coalesced int4 loads (rows*12 divisible by 4).
    {
        const int n_int4 = (rows * 12) >> 2;
        const int4* src  = (const int4*)(tb + (size_t)row_base * 12);
        int4* dst        = (int4*)s_bits;
        for (int i = tid; i < n_int4; i += THREADS)
            dst[i] = __ldcs(src + i);
    }
    __syncthreads();

    // Stage 2: pack 12 bits MSB-first per row.
    if (tid < rows) {
        const int* r = &s_bits[tid * 12];
        int b = 0;
#pragma unroll
        for (int c = 0; c < 12; c++)
            b |= r[c] << (11 - c);
        s_idx[tid] = b;
    }

    // PDL: wait for the build kernel's published LUT (HW wait, no L1 flush).
    asm volatile("griddepcontrol.wait;" ::: "memory");
    __syncthreads();

    // Stage 3: 8 float4 chunks per row, coalesced.
    float4* out4 = (float4*)out + (size_t)row_base * 8;

    if (rows == ROWS_PER_BLOCK) {
        float4 v[4];
#pragma unroll
        for (int j = 0; j < 4; j++) {
            const int t     = tid + j * THREADS;
            const int row   = t >> 3;
            const int chunk = t & 7;
            v[j] = __ldg((const float4*)&g_lut[s_idx[row] * 32] + chunk);
        }
#pragma unroll
        for (int j = 0; j < 4; j++)
            __stcs(&out4[tid + j * THREADS], v[j]);
    } else {
        const int ntasks = rows * 8;
        for (int t = tid; t < ntasks; t += THREADS) {
            const int row   = t >> 3;
            const int chunk = t & 7;
            float4 v = __ldg((const float4*)&g_lut[s_idx[row] * 32] + chunk);
            __stcs(&out4[t], v);
        }
    }
}

extern "C" void kernel_launch(void* const* d_in, const int* in_sizes, int n_in,
                              void* d_out, int out_size)
{
    const int*   tb   = (const int*)  d_in[0];  // type_bits      (B, 12) i32
    const float* pat  = (const float*)d_in[1];  // pattern_tables (4,3,4096) f32
    const float* pos  = (const float*)d_in[2];  // position_tables(4,5,4096) f32
    const int*   conn = (const int*)  d_in[3];  // position_conn  (4,5,12) i32

    int nrows   = in_sizes[0] / 12;
    int nblocks = (nrows + ROWS_PER_BLOCK - 1) / ROWS_PER_BLOCK;

    build_lut_kernel<<<128, 128>>>(pat, pos, conn);

    // PDL launch: gather may begin (and run its LUT-independent preamble)
    // while build_lut_kernel drains; griddepcontrol.wait orders the LUT reads.
    cudaLaunchConfig_t cfg = {};
    cfg.gridDim  = dim3((unsigned)nblocks, 1, 1);
    cfg.blockDim = dim3(THREADS, 1, 1);
    cfg.dynamicSmemBytes = 0;
    cfg.stream = 0;
    cudaLaunchAttribute attr[1];
    attr[0].id = cudaLaunchAttributeProgrammaticStreamSerialization;
    attr[0].val.programmaticStreamSerializationAllowed = 1;
    cfg.attrs    = attr;
    cfg.numAttrs = 1;

    cudaError_t err = cudaLaunchKernelEx(&cfg, gather_kernel, tb, (float*)d_out, nrows);
    if (err != cudaSuccess) {
        // Fallback: plain launch (serial after build) — still correct.
        gather_kernel<<<nblocks, THREADS>>>(tb, (float*)d_out, nrows);
    }
}

// round 12
// speedup vs baseline: 1.3247x; 1.3247x over previous
#include <cuda_runtime.h>
#include <cuda_bf16.h>

// 4096 possible 12-bit rows -> 32 floats each = 512 KB LUT in device global.
__device__ float g_lut[4096 * 32];

#define ROWS_PER_BLOCK 128
#define THREADS 256

// ---- LUT build kernel: 128 blocks x 128 threads = 16384 (b, s) items ----
// conn staged in smem (kills the serial per-thread LDG chain); the 5 pos
// gathers are independent -> MLP=5 on the only DRAM-latency chain.
__global__ __launch_bounds__(128)
void build_lut_kernel(const float* __restrict__ pat,
                      const float* __restrict__ pos,
                      const int*   __restrict__ conn)
{
    __shared__ int s_conn[240];
    for (int i = threadIdx.x; i < 240; i += 128)
        s_conn[i] = __ldg(&conn[i]);
    __syncthreads();

    const int idx = blockIdx.x * 128 + threadIdx.x;
    const int b = idx >> 2;
    const int s = idx & 3;

    const int bits3n = 3 * (s + 1);
    const int paddr  = b & ((1 << bits3n) - 1);   // last 3n columns, MSB-first

    float out[8];
    int pb = 0;
#pragma unroll
    for (int j = 0; j < 3; j++) {
        float v = __ldg(&pat[(s * 3 + j) * 4096 + paddr]);
        int bit = (v > 0.5f) ? 1 : 0;
        out[j]  = (float)bit;
        pb |= bit << j;
    }

    const int in_bits = bits3n + 3;
    const int nb      = (in_bits < 12) ? in_bits : 12;

    // Compute all 5 addresses first (ALU + smem only), then issue the 5
    // independent pos gathers together.
    int addrs[5];
#pragma unroll
    for (int k = 0; k < 5; k++) {
        int addr = 0;
        for (int j = 0; j < nb; j++) {
            int c   = s_conn[(s * 5 + k) * 12 + j] % in_bits;
            int bit = (c < bits3n) ? ((paddr >> (bits3n - 1 - c)) & 1)
                                   : ((pb >> (c - bits3n)) & 1);
            addr |= bit << j;
        }
        addrs[k] = addr;
    }
#pragma unroll
    for (int k = 0; k < 5; k++)
        out[3 + k] = __ldg(&pos[(s * 5 + k) * 4096 + addrs[k]]);

    float4* dst = (float4*)&g_lut[b * 32 + s * 8];
    dst[0] = ((const float4*)out)[0];
    dst[1] = ((const float4*)out)[1];
}

// ---- Gather kernel: R3 hot path, byte-identical (proven 55.1 us body) ----
__global__ __launch_bounds__(THREADS)
void gather_kernel(const int* __restrict__ tb,
                   float* __restrict__ out,
                   int nrows)
{
    __shared__ int s_bits[ROWS_PER_BLOCK * 12];   // 6144 B
    __shared__ int s_idx[ROWS_PER_BLOCK];

    const int tid      = threadIdx.x;
    const int row_base = blockIdx.x * ROWS_PER_BLOCK;
    const int rows     = min(ROWS_PER_BLOCK, nrows - row_base);
    if (rows <= 0) return;

    // Stage 1: coalesced int4 loads (rows*12 divisible by 4).
    {
        const int n_int4 = (rows * 12) >> 2;
        const int4* src  = (const int4*)(tb + (size_t)row_base * 12);
        int4* dst        = (int4*)s_bits;
        for (int i = tid; i < n_int4; i += THREADS)
            dst[i] = __ldcs(src + i);
    }
    __syncthreads();

    // Stage 2: pack 12 bits MSB-first per row.
    if (tid < rows) {
        const int* r = &s_bits[tid * 12];
        int b = 0;
#pragma unroll
        for (int c = 0; c < 12; c++)
            b |= r[c] << (11 - c);
        s_idx[tid] = b;
    }
    __syncthreads();

    // Stage 3: 8 float4 chunks per row, MLP=4, coalesced streaming stores.
    float4* out4 = (float4*)out + (size_t)row_base * 8;

    if (rows == ROWS_PER_BLOCK) {
        float4 v[4];
#pragma unroll
        for (int j = 0; j < 4; j++) {
            const int t     = tid + j * THREADS;
            const int row   = t >> 3;
            const int chunk = t & 7;
            v[j] = __ldg((const float4*)&g_lut[s_idx[row] * 32] + chunk);
        }
#pragma unroll
        for (int j = 0; j < 4; j++)
            __stcs(&out4[tid + j * THREADS], v[j]);
    } else {
        const int ntasks = rows * 8;
        for (int t = tid; t < ntasks; t += THREADS) {
            const int row   = t >> 3;
            const int chunk = t & 7;
            float4 v = __ldg((const float4*)&g_lut[s_idx[row] * 32] + chunk);
            __stcs(&out4[t], v);
        }
    }
}

extern "C" void kernel_launch(void* const* d_in, const int* in_sizes, int n_in,
                              void* d_out, int out_size)
{
    const int*   tb   = (const int*)  d_in[0];  // type_bits      (B, 12) i32
    const float* pat  = (const float*)d_in[1];  // pattern_tables (4,3,4096) f32
    const float* pos  = (const float*)d_in[2];  // position_tables(4,5,4096) f32
    const int*   conn = (const int*)  d_in[3];  // position_conn  (4,5,12) i32
    float*       out  = (float*)d_out;          // (B, 4, 8) f32

    int nrows   = in_sizes[0] / 12;
    int nblocks = (nrows + ROWS_PER_BLOCK - 1) / ROWS_PER_BLOCK;

    build_lut_kernel<<<128, 128>>>(pat, pos, conn);
    gather_kernel<<<nblocks, THREADS>>>(tb, out, nrows);
}